// round 9
// baseline (speedup 1.0000x reference)
#include <cuda_runtime.h>
#include <cuda_bf16.h>
#include <math.h>

// Problem constants
#define BB 2
#define TT 512
#define PP 16
#define EE 512
#define HH 8
#define DD 64
#define INTER 512
#define MM (BB*TT*PP)          // 16384 tokens
#define NHEADS (BB*PP*HH)      // 256 independent attention problems

// ---------------- scratch (static device globals; no allocation) ----------------
__device__ float g_q[MM*INTER];      // pre-rope q  [m][512]
__device__ float g_k[MM*INTER];      // pre-rope k
__device__ float g_v[MM*INTER];      // v
__device__ float g_Q[NHEADS*TT*DD];  // roped Q [bph][T][D]
__device__ float g_K[NHEADS*TT*DD];
__device__ float g_V[NHEADS*TT*DD];
__device__ float g_attn[MM*INTER];   // attention output [m][512]

// ---------------- generic fp32 GEMM: C[m][n] = sum_k A[m][k]*W[n][k] + bias[n] ----
// block tile 64x64, K-step 16, 256 threads, 4x4 per thread
__global__ __launch_bounds__(256) void gemm_tn_bias(
    const float* __restrict__ A, const float* __restrict__ W,
    const float* __restrict__ bias, float* __restrict__ C,
    int N, int K)
{
    __shared__ float As[16][64];
    __shared__ float Ws[16][64];
    const int tid = threadIdx.x;
    const int m0 = blockIdx.y * 64, n0 = blockIdx.x * 64;
    const int tx = tid & 15, ty = tid >> 4;

    const int r  = tid >> 2;        // 0..63
    const int c4 = (tid & 3) * 4;   // 0,4,8,12
    const float* Arow = A + (size_t)(m0 + r) * K + c4;
    const float* Wrow = W + (size_t)(n0 + r) * K + c4;

    float acc[4][4];
#pragma unroll
    for (int i = 0; i < 4; i++)
#pragma unroll
        for (int j = 0; j < 4; j++) acc[i][j] = 0.f;

    for (int k0 = 0; k0 < K; k0 += 16) {
        float4 a = *(const float4*)(Arow + k0);
        float4 w = *(const float4*)(Wrow + k0);
        As[c4+0][r] = a.x; As[c4+1][r] = a.y; As[c4+2][r] = a.z; As[c4+3][r] = a.w;
        Ws[c4+0][r] = w.x; Ws[c4+1][r] = w.y; Ws[c4+2][r] = w.z; Ws[c4+3][r] = w.w;
        __syncthreads();
#pragma unroll
        for (int kk = 0; kk < 16; kk++) {
            float4 av = *(const float4*)&As[kk][ty*4];
            float4 wv = *(const float4*)&Ws[kk][tx*4];
            float a4[4] = {av.x, av.y, av.z, av.w};
            float w4[4] = {wv.x, wv.y, wv.z, wv.w};
#pragma unroll
            for (int i = 0; i < 4; i++)
#pragma unroll
                for (int j = 0; j < 4; j++)
                    acc[i][j] = fmaf(a4[i], w4[j], acc[i][j]);
        }
        __syncthreads();
    }

#pragma unroll
    for (int i = 0; i < 4; i++) {
        int m = m0 + ty*4 + i;
#pragma unroll
        for (int j = 0; j < 4; j++) {
            int n = n0 + tx*4 + j;
            float b = bias ? bias[n] : 0.f;
            C[(size_t)m * N + n] = acc[i][j] + b;
        }
    }
}

// ---------------- RoPE + transpose [m][h*64] -> [bph][T][D] ----------------
__global__ void rope_transpose(const float* __restrict__ q,
                               const float* __restrict__ k,
                               const float* __restrict__ v,
                               float* __restrict__ Qo,
                               float* __restrict__ Ko,
                               float* __restrict__ Vo)
{
    int gid = blockIdx.x * blockDim.x + threadIdx.x;   // MM*HH*(DD/2)
    if (gid >= MM * HH * (DD/2)) return;
    int i = gid & 31;            // pair index 0..31
    int h = (gid >> 5) & 7;
    int m = gid >> 8;
    int p = m & 15;
    int t = (m >> 4) & 511;
    int b = m >> 13;
    int bph = ((b * PP + p) * HH + h);

    float inv  = powf(10000.f, -(float)(2*i) / (float)DD);
    float fr = (float)t * inv;
    float sn, cs;
    sincosf(fr, &sn, &cs);

    size_t src = (size_t)m * INTER + h * DD;
    float2 q2 = *(const float2*)(q + src + 2*i);
    float2 k2 = *(const float2*)(k + src + 2*i);
    float2 v2 = *(const float2*)(v + src + 2*i);

    float2 qo = make_float2(q2.x*cs - q2.y*sn, q2.y*cs + q2.x*sn);
    float2 ko = make_float2(k2.x*cs - k2.y*sn, k2.y*cs + k2.x*sn);

    size_t dst = (size_t)bph * TT * DD + (size_t)t * DD;
    ((float2*)(Qo + dst))[i] = qo;
    ((float2*)(Ko + dst))[i] = ko;
    ((float2*)(Vo + dst))[i] = v2;
}

// ---------------- causal flash attention, one query per thread ----------------
// grid (4 q-tiles of 128, 256 heads), 128 threads
__global__ __launch_bounds__(128) void attn_kernel(
    const float* __restrict__ Q, const float* __restrict__ K,
    const float* __restrict__ V, float* __restrict__ out)
{
    const int bph = blockIdx.y;
    const int qt  = blockIdx.x;
    const int tid = threadIdx.x;
    const int tq  = qt * 128 + tid;

    __shared__ float Ksh[64][64];
    __shared__ float Vsh[64][64];

    float q[DD], o[DD];
    {
        const float4* qsrc = (const float4*)(Q + ((size_t)bph * TT + tq) * DD);
#pragma unroll
        for (int d4 = 0; d4 < 16; d4++) {
            float4 t4 = qsrc[d4];
            q[d4*4+0] = t4.x; q[d4*4+1] = t4.y; q[d4*4+2] = t4.z; q[d4*4+3] = t4.w;
        }
    }
#pragma unroll
    for (int d = 0; d < DD; d++) o[d] = 0.f;

    float mrun = -1e30f, lrun = 0.f;
    const float scale = 0.125f;  // 1/sqrt(64)
    const int ntiles = 2 * qt + 2;   // key tiles 0 .. 2qt+1

    for (int kt = 0; kt < ntiles; kt++) {
        // cooperative K/V tile load (64 rows x 64 cols)
        {
            const float4* ks = (const float4*)(K + ((size_t)bph * TT + kt * 64) * DD);
            const float4* vs = (const float4*)(V + ((size_t)bph * TT + kt * 64) * DD);
            float4* kd = (float4*)&Ksh[0][0];
            float4* vd = (float4*)&Vsh[0][0];
#pragma unroll
            for (int it = 0; it < 8; it++) {
                int idx = tid + it * 128;       // 1024 float4 total
                kd[idx] = ks[idx];
                vd[idx] = vs[idx];
            }
        }
        __syncthreads();

        int nvalid = tq - kt * 64 + 1;
        if (nvalid > 64) nvalid = 64;

        for (int c0 = 0; c0 < nvalid; c0 += 16) {
            float s[16];
            float cmax = -1e30f;
#pragma unroll
            for (int j = 0; j < 16; j++) {
                int k = c0 + j;
                float acc = 0.f;
                const float4* kr = (const float4*)Ksh[k];
#pragma unroll
                for (int d4 = 0; d4 < 16; d4++) {
                    float4 kv = kr[d4];
                    acc = fmaf(q[d4*4+0], kv.x, acc);
                    acc = fmaf(q[d4*4+1], kv.y, acc);
                    acc = fmaf(q[d4*4+2], kv.z, acc);
                    acc = fmaf(q[d4*4+3], kv.w, acc);
                }
                s[j] = (k < nvalid) ? acc * scale : -1e30f;
                cmax = fmaxf(cmax, s[j]);
            }
            float mnew = fmaxf(mrun, cmax);
            float corr = __expf(mrun - mnew);
            lrun *= corr;
#pragma unroll
            for (int d = 0; d < DD; d++) o[d] *= corr;
#pragma unroll
            for (int j = 0; j < 16; j++) {
                float pj = __expf(s[j] - mnew);
                lrun += pj;
                const float4* vr = (const float4*)Vsh[c0 + j];
#pragma unroll
                for (int d4 = 0; d4 < 16; d4++) {
                    float4 vv = vr[d4];
                    o[d4*4+0] = fmaf(pj, vv.x, o[d4*4+0]);
                    o[d4*4+1] = fmaf(pj, vv.y, o[d4*4+1]);
                    o[d4*4+2] = fmaf(pj, vv.z, o[d4*4+2]);
                    o[d4*4+3] = fmaf(pj, vv.w, o[d4*4+3]);
                }
            }
            mrun = mnew;
        }
        __syncthreads();
    }

    // write back into [m][h*64+d] token-major layout
    float invl = 1.f / lrun;
    int h = bph & 7, p = (bph >> 3) & 15, b = bph >> 7;
    float* dst = g_attn + (((size_t)(b * TT + tq) * PP + p) * INTER + h * DD);
    float4* dst4 = (float4*)dst;
#pragma unroll
    for (int d4 = 0; d4 < 16; d4++) {
        float4 w = make_float4(o[d4*4+0]*invl, o[d4*4+1]*invl,
                               o[d4*4+2]*invl, o[d4*4+3]*invl);
        dst4[d4] = w;
    }
}

// ---------------- host launcher ----------------
extern "C" void kernel_launch(void* const* d_in, const int* in_sizes, int n_in,
                              void* d_out, int out_size)
{
    (void)in_sizes; (void)n_in; (void)out_size;
    const float* x      = (const float*)d_in[0];
    const float* q_w    = (const float*)d_in[1];
    const float* q_b    = (const float*)d_in[2];
    const float* k_w    = (const float*)d_in[3];
    const float* k_b    = (const float*)d_in[4];
    const float* v_w    = (const float*)d_in[5];
    const float* v_b    = (const float*)d_in[6];
    const float* proj_w = (const float*)d_in[7];
    float* out = (float*)d_out;

    float *pq, *pk, *pv, *pQ, *pK, *pV, *pattn;
    cudaGetSymbolAddress((void**)&pq, g_q);
    cudaGetSymbolAddress((void**)&pk, g_k);
    cudaGetSymbolAddress((void**)&pv, g_v);
    cudaGetSymbolAddress((void**)&pQ, g_Q);
    cudaGetSymbolAddress((void**)&pK, g_K);
    cudaGetSymbolAddress((void**)&pV, g_V);
    cudaGetSymbolAddress((void**)&pattn, g_attn);

    dim3 gqkv(INTER / 64, MM / 64);   // (8, 256)
    gemm_tn_bias<<<gqkv, 256>>>(x, q_w, q_b, pq, INTER, EE);
    gemm_tn_bias<<<gqkv, 256>>>(x, k_w, k_b, pk, INTER, EE);
    gemm_tn_bias<<<gqkv, 256>>>(x, v_w, v_b, pv, INTER, EE);

    int nrope = MM * HH * (DD / 2);
    rope_transpose<<<(nrope + 255) / 256, 256>>>(pq, pk, pv, pQ, pK, pV);

    dim3 gattn(TT / 128, NHEADS);     // (4, 256)
    attn_kernel<<<gattn, 128>>>(pQ, pK, pV, pattn);

    dim3 gproj(EE / 64, MM / 64);     // (8, 256)
    gemm_tn_bias<<<gproj, 256>>>(pattn, proj_w, nullptr, out, EE, INTER);
}

// round 10
// speedup vs baseline: 1.0020x; 1.0020x over previous
#include <cuda_runtime.h>
#include <cuda_bf16.h>
#include <math.h>

// Problem constants
#define BB 2
#define TT 512
#define PP 16
#define EE 512
#define HH 8
#define DD 64
#define INTER 512
#define MM (BB*TT*PP)          // 16384 tokens
#define NHEADS (BB*PP*HH)      // 256 independent attention problems

// ---------------- scratch (static device globals; no allocation) ----------------
__device__ float g_q[MM*INTER];      // pre-rope q  [m][512]
__device__ float g_k[MM*INTER];      // pre-rope k
__device__ float g_v[MM*INTER];      // v
__device__ float g_Q[NHEADS*TT*DD];  // roped Q [bph][T][D]
__device__ float g_K[NHEADS*TT*DD];
__device__ float g_V[NHEADS*TT*DD];
__device__ float g_attn[MM*INTER];   // attention output [m][512]

// ---------------- generic fp32 GEMM: C[m][n] = sum_k A[m][k]*W[n][k] + bias[n] ----
// block tile 64x64, K-step 16, 256 threads, 4x4 per thread
__global__ __launch_bounds__(256) void gemm_tn_bias(
    const float* __restrict__ A, const float* __restrict__ W,
    const float* __restrict__ bias, float* __restrict__ C,
    int N, int K)
{
    __shared__ float As[16][64];
    __shared__ float Ws[16][64];
    const int tid = threadIdx.x;
    const int m0 = blockIdx.y * 64, n0 = blockIdx.x * 64;
    const int tx = tid & 15, ty = tid >> 4;

    const int r  = tid >> 2;        // 0..63
    const int c4 = (tid & 3) * 4;   // 0,4,8,12
    const float* Arow = A + (size_t)(m0 + r) * K + c4;
    const float* Wrow = W + (size_t)(n0 + r) * K + c4;

    float acc[4][4];
#pragma unroll
    for (int i = 0; i < 4; i++)
#pragma unroll
        for (int j = 0; j < 4; j++) acc[i][j] = 0.f;

    for (int k0 = 0; k0 < K; k0 += 16) {
        float4 a = *(const float4*)(Arow + k0);
        float4 w = *(const float4*)(Wrow + k0);
        As[c4+0][r] = a.x; As[c4+1][r] = a.y; As[c4+2][r] = a.z; As[c4+3][r] = a.w;
        Ws[c4+0][r] = w.x; Ws[c4+1][r] = w.y; Ws[c4+2][r] = w.z; Ws[c4+3][r] = w.w;
        __syncthreads();
#pragma unroll
        for (int kk = 0; kk < 16; kk++) {
            float4 av = *(const float4*)&As[kk][ty*4];
            float4 wv = *(const float4*)&Ws[kk][tx*4];
            float a4[4] = {av.x, av.y, av.z, av.w};
            float w4[4] = {wv.x, wv.y, wv.z, wv.w};
#pragma unroll
            for (int i = 0; i < 4; i++)
#pragma unroll
                for (int j = 0; j < 4; j++)
                    acc[i][j] = fmaf(a4[i], w4[j], acc[i][j]);
        }
        __syncthreads();
    }

#pragma unroll
    for (int i = 0; i < 4; i++) {
        int m = m0 + ty*4 + i;
#pragma unroll
        for (int j = 0; j < 4; j++) {
            int n = n0 + tx*4 + j;
            float b = bias ? bias[n] : 0.f;
            C[(size_t)m * N + n] = acc[i][j] + b;
        }
    }
}

// ---------------- RoPE + transpose [m][h*64] -> [bph][T][D] ----------------
__global__ void rope_transpose(const float* __restrict__ q,
                               const float* __restrict__ k,
                               const float* __restrict__ v,
                               float* __restrict__ Qo,
                               float* __restrict__ Ko,
                               float* __restrict__ Vo)
{
    int gid = blockIdx.x * blockDim.x + threadIdx.x;   // MM*HH*(DD/2)
    if (gid >= MM * HH * (DD/2)) return;
    int i = gid & 31;            // pair index 0..31
    int h = (gid >> 5) & 7;
    int m = gid >> 8;
    int p = m & 15;
    int t = (m >> 4) & 511;
    int b = m >> 13;
    int bph = ((b * PP + p) * HH + h);

    float inv  = powf(10000.f, -(float)(2*i) / (float)DD);
    float fr = (float)t * inv;
    float sn, cs;
    sincosf(fr, &sn, &cs);

    size_t src = (size_t)m * INTER + h * DD;
    float2 q2 = *(const float2*)(q + src + 2*i);
    float2 k2 = *(const float2*)(k + src + 2*i);
    float2 v2 = *(const float2*)(v + src + 2*i);

    float2 qo = make_float2(q2.x*cs - q2.y*sn, q2.y*cs + q2.x*sn);
    float2 ko = make_float2(k2.x*cs - k2.y*sn, k2.y*cs + k2.x*sn);

    size_t dst = (size_t)bph * TT * DD + (size_t)t * DD;
    ((float2*)(Qo + dst))[i] = qo;
    ((float2*)(Ko + dst))[i] = ko;
    ((float2*)(Vo + dst))[i] = v2;
}

// ---------------- causal flash attention, one query per thread ----------------
// grid (4 q-tiles of 128, 256 heads), 128 threads
__global__ __launch_bounds__(128) void attn_kernel(
    const float* __restrict__ Q, const float* __restrict__ K,
    const float* __restrict__ V, float* __restrict__ out)
{
    const int bph = blockIdx.y;
    const int qt  = blockIdx.x;
    const int tid = threadIdx.x;
    const int tq  = qt * 128 + tid;

    __shared__ float Ksh[64][64];
    __shared__ float Vsh[64][64];

    float q[DD], o[DD];
    {
        const float4* qsrc = (const float4*)(Q + ((size_t)bph * TT + tq) * DD);
#pragma unroll
        for (int d4 = 0; d4 < 16; d4++) {
            float4 t4 = qsrc[d4];
            q[d4*4+0] = t4.x; q[d4*4+1] = t4.y; q[d4*4+2] = t4.z; q[d4*4+3] = t4.w;
        }
    }
#pragma unroll
    for (int d = 0; d < DD; d++) o[d] = 0.f;

    float mrun = -1e30f, lrun = 0.f;
    const float scale = 0.125f;  // 1/sqrt(64)
    const int ntiles = 2 * qt + 2;   // key tiles 0 .. 2qt+1

    for (int kt = 0; kt < ntiles; kt++) {
        // cooperative K/V tile load (64 rows x 64 cols)
        {
            const float4* ks = (const float4*)(K + ((size_t)bph * TT + kt * 64) * DD);
            const float4* vs = (const float4*)(V + ((size_t)bph * TT + kt * 64) * DD);
            float4* kd = (float4*)&Ksh[0][0];
            float4* vd = (float4*)&Vsh[0][0];
#pragma unroll
            for (int it = 0; it < 8; it++) {
                int idx = tid + it * 128;       // 1024 float4 total
                kd[idx] = ks[idx];
                vd[idx] = vs[idx];
            }
        }
        __syncthreads();

        int nvalid = tq - kt * 64 + 1;
        if (nvalid > 64) nvalid = 64;

        for (int c0 = 0; c0 < nvalid; c0 += 16) {
            float s[16];
            float cmax = -1e30f;
#pragma unroll
            for (int j = 0; j < 16; j++) {
                int k = c0 + j;
                float acc = 0.f;
                const float4* kr = (const float4*)Ksh[k];
#pragma unroll
                for (int d4 = 0; d4 < 16; d4++) {
                    float4 kv = kr[d4];
                    acc = fmaf(q[d4*4+0], kv.x, acc);
                    acc = fmaf(q[d4*4+1], kv.y, acc);
                    acc = fmaf(q[d4*4+2], kv.z, acc);
                    acc = fmaf(q[d4*4+3], kv.w, acc);
                }
                s[j] = (k < nvalid) ? acc * scale : -1e30f;
                cmax = fmaxf(cmax, s[j]);
            }
            float mnew = fmaxf(mrun, cmax);
            float corr = __expf(mrun - mnew);
            lrun *= corr;
#pragma unroll
            for (int d = 0; d < DD; d++) o[d] *= corr;
#pragma unroll
            for (int j = 0; j < 16; j++) {
                float pj = __expf(s[j] - mnew);
                lrun += pj;
                const float4* vr = (const float4*)Vsh[c0 + j];
#pragma unroll
                for (int d4 = 0; d4 < 16; d4++) {
                    float4 vv = vr[d4];
                    o[d4*4+0] = fmaf(pj, vv.x, o[d4*4+0]);
                    o[d4*4+1] = fmaf(pj, vv.y, o[d4*4+1]);
                    o[d4*4+2] = fmaf(pj, vv.z, o[d4*4+2]);
                    o[d4*4+3] = fmaf(pj, vv.w, o[d4*4+3]);
                }
            }
            mrun = mnew;
        }
        __syncthreads();
    }

    // write back into [m][h*64+d] token-major layout
    float invl = 1.f / lrun;
    int h = bph & 7, p = (bph >> 3) & 15, b = bph >> 7;
    float* dst = g_attn + (((size_t)(b * TT + tq) * PP + p) * INTER + h * DD);
    float4* dst4 = (float4*)dst;
#pragma unroll
    for (int d4 = 0; d4 < 16; d4++) {
        float4 w = make_float4(o[d4*4+0]*invl, o[d4*4+1]*invl,
                               o[d4*4+2]*invl, o[d4*4+3]*invl);
        dst4[d4] = w;
    }
}

// ---------------- host launcher ----------------
extern "C" void kernel_launch(void* const* d_in, const int* in_sizes, int n_in,
                              void* d_out, int out_size)
{
    (void)in_sizes; (void)n_in; (void)out_size;
    const float* x      = (const float*)d_in[0];
    const float* q_w    = (const float*)d_in[1];
    const float* q_b    = (const float*)d_in[2];
    const float* k_w    = (const float*)d_in[3];
    const float* k_b    = (const float*)d_in[4];
    const float* v_w    = (const float*)d_in[5];
    const float* v_b    = (const float*)d_in[6];
    const float* proj_w = (const float*)d_in[7];
    float* out = (float*)d_out;

    float *pq, *pk, *pv, *pQ, *pK, *pV, *pattn;
    cudaGetSymbolAddress((void**)&pq, g_q);
    cudaGetSymbolAddress((void**)&pk, g_k);
    cudaGetSymbolAddress((void**)&pv, g_v);
    cudaGetSymbolAddress((void**)&pQ, g_Q);
    cudaGetSymbolAddress((void**)&pK, g_K);
    cudaGetSymbolAddress((void**)&pV, g_V);
    cudaGetSymbolAddress((void**)&pattn, g_attn);

    dim3 gqkv(INTER / 64, MM / 64);   // (8, 256)
    gemm_tn_bias<<<gqkv, 256>>>(x, q_w, q_b, pq, INTER, EE);
    gemm_tn_bias<<<gqkv, 256>>>(x, k_w, k_b, pk, INTER, EE);
    gemm_tn_bias<<<gqkv, 256>>>(x, v_w, v_b, pv, INTER, EE);

    int nrope = MM * HH * (DD / 2);
    rope_transpose<<<(nrope + 255) / 256, 256>>>(pq, pk, pv, pQ, pK, pV);

    dim3 gattn(TT / 128, NHEADS);     // (4, 256)
    attn_kernel<<<gattn, 128>>>(pQ, pK, pV, pattn);

    dim3 gproj(EE / 64, MM / 64);     // (8, 256)
    gemm_tn_bias<<<gproj, 256>>>(pattn, proj_w, nullptr, out, EE, INTER);
}

// round 11
// speedup vs baseline: 1.0030x; 1.0009x over previous
#include <cuda_runtime.h>
#include <cuda_bf16.h>
#include <math.h>

// Problem constants
#define BB 2
#define TT 512
#define PP 16
#define EE 512
#define HH 8
#define DD 64
#define INTER 512
#define MM (BB*TT*PP)          // 16384 tokens
#define NHEADS (BB*PP*HH)      // 256 independent attention problems

// ---------------- scratch (static device globals; no allocation) ----------------
__device__ float g_q[MM*INTER];      // pre-rope q  [m][512]
__device__ float g_k[MM*INTER];      // pre-rope k
__device__ float g_v[MM*INTER];      // v
__device__ float g_Q[NHEADS*TT*DD];  // roped Q [bph][T][D]
__device__ float g_K[NHEADS*TT*DD];
__device__ float g_V[NHEADS*TT*DD];
__device__ float g_attn[MM*INTER];   // attention output [m][512]

// ---------------- generic fp32 GEMM: C[m][n] = sum_k A[m][k]*W[n][k] + bias[n] ----
// block tile 64x64, K-step 16, 256 threads, 4x4 per thread
__global__ __launch_bounds__(256) void gemm_tn_bias(
    const float* __restrict__ A, const float* __restrict__ W,
    const float* __restrict__ bias, float* __restrict__ C,
    int N, int K)
{
    __shared__ float As[16][64];
    __shared__ float Ws[16][64];
    const int tid = threadIdx.x;
    const int m0 = blockIdx.y * 64, n0 = blockIdx.x * 64;
    const int tx = tid & 15, ty = tid >> 4;

    const int r  = tid >> 2;        // 0..63
    const int c4 = (tid & 3) * 4;   // 0,4,8,12
    const float* Arow = A + (size_t)(m0 + r) * K + c4;
    const float* Wrow = W + (size_t)(n0 + r) * K + c4;

    float acc[4][4];
#pragma unroll
    for (int i = 0; i < 4; i++)
#pragma unroll
        for (int j = 0; j < 4; j++) acc[i][j] = 0.f;

    for (int k0 = 0; k0 < K; k0 += 16) {
        float4 a = *(const float4*)(Arow + k0);
        float4 w = *(const float4*)(Wrow + k0);
        As[c4+0][r] = a.x; As[c4+1][r] = a.y; As[c4+2][r] = a.z; As[c4+3][r] = a.w;
        Ws[c4+0][r] = w.x; Ws[c4+1][r] = w.y; Ws[c4+2][r] = w.z; Ws[c4+3][r] = w.w;
        __syncthreads();
#pragma unroll
        for (int kk = 0; kk < 16; kk++) {
            float4 av = *(const float4*)&As[kk][ty*4];
            float4 wv = *(const float4*)&Ws[kk][tx*4];
            float a4[4] = {av.x, av.y, av.z, av.w};
            float w4[4] = {wv.x, wv.y, wv.z, wv.w};
#pragma unroll
            for (int i = 0; i < 4; i++)
#pragma unroll
                for (int j = 0; j < 4; j++)
                    acc[i][j] = fmaf(a4[i], w4[j], acc[i][j]);
        }
        __syncthreads();
    }

#pragma unroll
    for (int i = 0; i < 4; i++) {
        int m = m0 + ty*4 + i;
#pragma unroll
        for (int j = 0; j < 4; j++) {
            int n = n0 + tx*4 + j;
            float b = bias ? bias[n] : 0.f;
            C[(size_t)m * N + n] = acc[i][j] + b;
        }
    }
}

// ---------------- RoPE + transpose [m][h*64] -> [bph][T][D] ----------------
__global__ void rope_transpose(const float* __restrict__ q,
                               const float* __restrict__ k,
                               const float* __restrict__ v,
                               float* __restrict__ Qo,
                               float* __restrict__ Ko,
                               float* __restrict__ Vo)
{
    int gid = blockIdx.x * blockDim.x + threadIdx.x;   // MM*HH*(DD/2)
    if (gid >= MM * HH * (DD/2)) return;
    int i = gid & 31;            // pair index 0..31
    int h = (gid >> 5) & 7;
    int m = gid >> 8;
    int p = m & 15;
    int t = (m >> 4) & 511;
    int b = m >> 13;
    int bph = ((b * PP + p) * HH + h);

    float inv  = powf(10000.f, -(float)(2*i) / (float)DD);
    float fr = (float)t * inv;
    float sn, cs;
    sincosf(fr, &sn, &cs);

    size_t src = (size_t)m * INTER + h * DD;
    float2 q2 = *(const float2*)(q + src + 2*i);
    float2 k2 = *(const float2*)(k + src + 2*i);
    float2 v2 = *(const float2*)(v + src + 2*i);

    float2 qo = make_float2(q2.x*cs - q2.y*sn, q2.y*cs + q2.x*sn);
    float2 ko = make_float2(k2.x*cs - k2.y*sn, k2.y*cs + k2.x*sn);

    size_t dst = (size_t)bph * TT * DD + (size_t)t * DD;
    ((float2*)(Qo + dst))[i] = qo;
    ((float2*)(Ko + dst))[i] = ko;
    ((float2*)(Vo + dst))[i] = v2;
}

// ---------------- causal flash attention, one query per thread ----------------
// grid (4 q-tiles of 128, 256 heads), 128 threads
__global__ __launch_bounds__(128) void attn_kernel(
    const float* __restrict__ Q, const float* __restrict__ K,
    const float* __restrict__ V, float* __restrict__ out)
{
    const int bph = blockIdx.y;
    const int qt  = blockIdx.x;
    const int tid = threadIdx.x;
    const int tq  = qt * 128 + tid;

    __shared__ float Ksh[64][64];
    __shared__ float Vsh[64][64];

    float q[DD], o[DD];
    {
        const float4* qsrc = (const float4*)(Q + ((size_t)bph * TT + tq) * DD);
#pragma unroll
        for (int d4 = 0; d4 < 16; d4++) {
            float4 t4 = qsrc[d4];
            q[d4*4+0] = t4.x; q[d4*4+1] = t4.y; q[d4*4+2] = t4.z; q[d4*4+3] = t4.w;
        }
    }
#pragma unroll
    for (int d = 0; d < DD; d++) o[d] = 0.f;

    float mrun = -1e30f, lrun = 0.f;
    const float scale = 0.125f;  // 1/sqrt(64)
    const int ntiles = 2 * qt + 2;   // key tiles 0 .. 2qt+1

    for (int kt = 0; kt < ntiles; kt++) {
        // cooperative K/V tile load (64 rows x 64 cols)
        {
            const float4* ks = (const float4*)(K + ((size_t)bph * TT + kt * 64) * DD);
            const float4* vs = (const float4*)(V + ((size_t)bph * TT + kt * 64) * DD);
            float4* kd = (float4*)&Ksh[0][0];
            float4* vd = (float4*)&Vsh[0][0];
#pragma unroll
            for (int it = 0; it < 8; it++) {
                int idx = tid + it * 128;       // 1024 float4 total
                kd[idx] = ks[idx];
                vd[idx] = vs[idx];
            }
        }
        __syncthreads();

        int nvalid = tq - kt * 64 + 1;
        if (nvalid > 64) nvalid = 64;

        for (int c0 = 0; c0 < nvalid; c0 += 16) {
            float s[16];
            float cmax = -1e30f;
#pragma unroll
            for (int j = 0; j < 16; j++) {
                int k = c0 + j;
                float acc = 0.f;
                const float4* kr = (const float4*)Ksh[k];
#pragma unroll
                for (int d4 = 0; d4 < 16; d4++) {
                    float4 kv = kr[d4];
                    acc = fmaf(q[d4*4+0], kv.x, acc);
                    acc = fmaf(q[d4*4+1], kv.y, acc);
                    acc = fmaf(q[d4*4+2], kv.z, acc);
                    acc = fmaf(q[d4*4+3], kv.w, acc);
                }
                s[j] = (k < nvalid) ? acc * scale : -1e30f;
                cmax = fmaxf(cmax, s[j]);
            }
            float mnew = fmaxf(mrun, cmax);
            float corr = __expf(mrun - mnew);
            lrun *= corr;
#pragma unroll
            for (int d = 0; d < DD; d++) o[d] *= corr;
#pragma unroll
            for (int j = 0; j < 16; j++) {
                float pj = __expf(s[j] - mnew);
                lrun += pj;
                const float4* vr = (const float4*)Vsh[c0 + j];
#pragma unroll
                for (int d4 = 0; d4 < 16; d4++) {
                    float4 vv = vr[d4];
                    o[d4*4+0] = fmaf(pj, vv.x, o[d4*4+0]);
                    o[d4*4+1] = fmaf(pj, vv.y, o[d4*4+1]);
                    o[d4*4+2] = fmaf(pj, vv.z, o[d4*4+2]);
                    o[d4*4+3] = fmaf(pj, vv.w, o[d4*4+3]);
                }
            }
            mrun = mnew;
        }
        __syncthreads();
    }

    // write back into [m][h*64+d] token-major layout
    float invl = 1.f / lrun;
    int h = bph & 7, p = (bph >> 3) & 15, b = bph >> 7;
    float* dst = g_attn + (((size_t)(b * TT + tq) * PP + p) * INTER + h * DD);
    float4* dst4 = (float4*)dst;
#pragma unroll
    for (int d4 = 0; d4 < 16; d4++) {
        float4 w = make_float4(o[d4*4+0]*invl, o[d4*4+1]*invl,
                               o[d4*4+2]*invl, o[d4*4+3]*invl);
        dst4[d4] = w;
    }
}

// ---------------- host launcher ----------------
extern "C" void kernel_launch(void* const* d_in, const int* in_sizes, int n_in,
                              void* d_out, int out_size)
{
    (void)in_sizes; (void)n_in; (void)out_size;
    const float* x      = (const float*)d_in[0];
    const float* q_w    = (const float*)d_in[1];
    const float* q_b    = (const float*)d_in[2];
    const float* k_w    = (const float*)d_in[3];
    const float* k_b    = (const float*)d_in[4];
    const float* v_w    = (const float*)d_in[5];
    const float* v_b    = (const float*)d_in[6];
    const float* proj_w = (const float*)d_in[7];
    float* out = (float*)d_out;

    float *pq, *pk, *pv, *pQ, *pK, *pV, *pattn;
    cudaGetSymbolAddress((void**)&pq, g_q);
    cudaGetSymbolAddress((void**)&pk, g_k);
    cudaGetSymbolAddress((void**)&pv, g_v);
    cudaGetSymbolAddress((void**)&pQ, g_Q);
    cudaGetSymbolAddress((void**)&pK, g_K);
    cudaGetSymbolAddress((void**)&pV, g_V);
    cudaGetSymbolAddress((void**)&pattn, g_attn);

    dim3 gqkv(INTER / 64, MM / 64);   // (8, 256)
    gemm_tn_bias<<<gqkv, 256>>>(x, q_w, q_b, pq, INTER, EE);
    gemm_tn_bias<<<gqkv, 256>>>(x, k_w, k_b, pk, INTER, EE);
    gemm_tn_bias<<<gqkv, 256>>>(x, v_w, v_b, pv, INTER, EE);

    int nrope = MM * HH * (DD / 2);
    rope_transpose<<<(nrope + 255) / 256, 256>>>(pq, pk, pv, pQ, pK, pV);

    dim3 gattn(TT / 128, NHEADS);     // (4, 256)
    attn_kernel<<<gattn, 128>>>(pQ, pK, pV, pattn);

    dim3 gproj(EE / 64, MM / 64);     // (8, 256)
    gemm_tn_bias<<<gproj, 256>>>(pattn, proj_w, nullptr, out, EE, INTER);
}